// round 6
// baseline (speedup 1.0000x reference)
#include <cuda_runtime.h>
#include <cuda_bf16.h>
#include <stdint.h>

#define BATCH 8
#define NN    1024
#define FF    128

// ---------------- scratch (no allocations allowed -> __device__ globals) --------
__device__ float    g_H[(size_t)BATCH * 12 * NN * FF];     // 48 MB
__device__ float    g_outacc[(size_t)BATCH * NN * FF];     // 4 MB (self contribution)
__device__ float    g_part[12][(size_t)BATCH * NN * FF];   // 48 MB per-op partials
__device__ float    g_esrc[BATCH * 12 * NN];
__device__ float    g_edst[BATCH * 12 * NN];
__device__ float    g_Htot[BATCH * 12 * FF];
__device__ uint32_t g_rowbits[(size_t)BATCH * 6 * NN * 32];  // rel 0-2, 6-8 row masks
__device__ uint32_t g_bitsT[(size_t)BATCH * 3 * NN * 32];    // rel 6-8 transposed masks
__device__ uint32_t g_dbits[BATCH * 3 * 32];                 // diag masks (rel 3-5)

// pack two fp32 into bf16x2 word (lo -> low half, hi -> high half)
__device__ __forceinline__ uint32_t pack_bf16x2(float lo, float hi)
{
    uint32_t r;
    asm("cvt.rn.bf16x2.f32 %0, %1, %2;" : "=r"(r) : "f"(hi), "f"(lo));
    return r;
}

// =========== fused bitpack: row masks, transposed masks, diag, Htot zero ========
__global__ __launch_bounds__(256) void bitpack_kernel(const float* __restrict__ adjs)
{
    const int slab = blockIdx.x, y = blockIdx.y, b = blockIdx.z;
    const int warp = threadIdx.x >> 5, lane = threadIdx.x & 31;

    if (y == 6) {
        if (slab < 3) {                       // diag masks for rel 3..5
            #pragma unroll
            for (int rr = 0; rr < 4; rr++) {
                const int i = rr * 256 + threadIdx.x;
                float v = adjs[(((size_t)(b * 9 + 3 + slab)) * NN + i) * NN + i];
                unsigned m = __ballot_sync(0xffffffffu, v > 0.f);
                if (lane == 0) g_dbits[(b * 3 + slab) * 32 + (i >> 5)] = m;
            }
        } else if (slab == 3 && b == 0) {     // zero Htot (before gemm's atomics)
            for (int t = threadIdx.x; t < BATCH * 12 * FF; t += 256) g_Htot[t] = 0.f;
        }
        return;
    }

    const bool doT = (y >= 3);
    const int rel = doT ? (y + 3) : y;        // y 0-2 -> rel 0-2 ; y 3-5 -> rel 6-8
    __shared__ uint32_t sw[32 * 32];

    #pragma unroll
    for (int rr = 0; rr < 4; rr++) {
        const int row = slab * 32 + warp * 4 + rr;
        const float* rp = adjs + (((size_t)(b * 9 + rel)) * NN + row) * NN;
        uint32_t myw = 0;
        #pragma unroll 4
        for (int it = 0; it < 32; it++) {
            float v = rp[it * 32 + lane];
            unsigned mm = __ballot_sync(0xffffffffu, v > 0.f);
            if (lane == it) myw = mm;
        }
        g_rowbits[(((size_t)(b * 6 + y)) * NN + row) * 32 + lane] = myw;
        if (doT) sw[(warp * 4 + rr) * 32 + lane] = myw;
    }
    if (doT) {
        __syncthreads();
        for (int c = threadIdx.x; c < NN; c += 256) {
            const int word = c >> 5, bit = c & 31;
            uint32_t t = 0;
            #pragma unroll
            for (int r = 0; r < 32; r++)
                t |= ((sw[r * 32 + word] >> bit) & 1u) << r;
            g_bitsT[(((size_t)(b * 3 + (y - 3))) * NN + c) * 32 + slab] = t;
        }
    }
}

// =============================== tf32 GEMM ======================================
__device__ __forceinline__ uint32_t f2tf32(float f)
{
    uint32_t r;
    asm("cvt.rna.tf32.f32 %0, %1;" : "=r"(r) : "f"(f));
    return r;
}

__device__ __forceinline__ void mma_tf32(float4& d, const uint4 a, const uint2 b)
{
    asm volatile(
        "mma.sync.aligned.m16n8k8.row.col.f32.tf32.tf32.f32 "
        "{%0,%1,%2,%3}, {%4,%5,%6,%7}, {%8,%9}, {%0,%1,%2,%3};"
        : "+f"(d.x), "+f"(d.y), "+f"(d.z), "+f"(d.w)
        : "r"(a.x), "r"(a.y), "r"(a.z), "r"(a.w), "r"(b.x), "r"(b.y));
}

#define GEMM_SMEM (32768 * 4)

__global__ __launch_bounds__(512) void gemm_kernel(
    const float* __restrict__ x,
    const float* __restrict__ fc_w,  const float* __restrict__ fc_b,
    const float* __restrict__ fwd_w, const float* __restrict__ fwd_b,
    const float* __restrict__ bwd_w, const float* __restrict__ bwd_b,
    const float* __restrict__ self_w, const float* __restrict__ self_b,
    const float* __restrict__ bias)
{
    extern __shared__ uint32_t sm[];
    uint32_t* As = sm;
    uint32_t* Ws = sm + 16384;

    const int rb = blockIdx.x, r = blockIdx.y, b = blockIdx.z;
    const int tid = threadIdx.x;

    const float* X = x + (size_t)b * NN * FF + (size_t)rb * 128 * FF;
    const float* Wp; const float* bv; const float* bv2 = nullptr; float* dst;
    if (r < 6)       { Wp = fc_w  + r * FF * FF;       bv = fc_b  + r * FF;
                       dst = g_H + ((size_t)(b * 12 + r)) * NN * FF; }
    else if (r < 9)  { Wp = fwd_w + (r - 6) * FF * FF; bv = fwd_b + (r - 6) * FF;
                       dst = g_H + ((size_t)(b * 12 + r)) * NN * FF; }
    else if (r < 12) { Wp = bwd_w + (r - 9) * FF * FF; bv = bwd_b + (r - 9) * FF;
                       dst = g_H + ((size_t)(b * 12 + r)) * NN * FF; }
    else             { Wp = self_w; bv = self_b; bv2 = bias;
                       dst = g_outacc + (size_t)b * NN * FF; }

    for (int t = tid; t < 4096; t += 512) {
        const int row = t >> 5;
        const int c = (t & 31) << 2;
        float4 v = *(const float4*)(X + (size_t)row * FF + c);
        const int m = row >> 4, lr = row & 15;
        const int s = c >> 3;
        const int reg = (lr >> 3) + ((c & 4) ? 2 : 0);
        uint32_t* base = As + (((m << 4) + s) << 7) + (((lr & 7) << 2) << 2) + reg;
        base[0]  = f2tf32(v.x);
        base[4]  = f2tf32(v.y);
        base[8]  = f2tf32(v.z);
        base[12] = f2tf32(v.w);
    }
    for (int t = tid; t < 4096; t += 512) {
        const int n = t >> 5;
        const int k = (t & 31) << 2;
        float4 v = *(const float4*)(Wp + (size_t)n * FF + k);
        const int nt = n >> 3;
        const int s = k >> 3;
        const int reg = (k & 4) ? 1 : 0;
        uint32_t* base = Ws + (((nt << 4) + s) << 6) + (((n & 7) << 2) << 1) + reg;
        base[0] = f2tf32(v.x);
        base[2] = f2tf32(v.y);
        base[4] = f2tf32(v.z);
        base[6] = f2tf32(v.w);
    }
    __syncthreads();

    const int warp = tid >> 5, lane = tid & 31;
    const int wm = warp >> 2, wn = warp & 3;

    float4 acc[2][4];
    #pragma unroll
    for (int i = 0; i < 2; i++)
        #pragma unroll
        for (int j = 0; j < 4; j++) acc[i][j] = make_float4(0.f, 0.f, 0.f, 0.f);

    #pragma unroll
    for (int s = 0; s < 16; s++) {
        uint4 a[2]; uint2 bb[4];
        #pragma unroll
        for (int i = 0; i < 2; i++)
            a[i] = *(const uint4*)(As + ((((wm * 2 + i) << 4) + s) << 7) + (lane << 2));
        #pragma unroll
        for (int j = 0; j < 4; j++)
            bb[j] = *(const uint2*)(Ws + ((((wn * 4 + j) << 4) + s) << 6) + (lane << 1));
        #pragma unroll
        for (int i = 0; i < 2; i++)
            #pragma unroll
            for (int j = 0; j < 4; j++)
                mma_tf32(acc[i][j], a[i], bb[j]);
    }

    const int g = lane >> 2, t4 = lane & 3;
    float b0[4], b1[4];
    #pragma unroll
    for (int j = 0; j < 4; j++) {
        const int col = (wn * 4 + j) * 8 + 2 * t4;
        b0[j] = bv[col];     b1[j] = bv[col + 1];
        if (bv2) { b0[j] += bv2[col]; b1[j] += bv2[col + 1]; }
    }
    #pragma unroll
    for (int i = 0; i < 2; i++) {
        const int row0 = rb * 128 + (wm * 2 + i) * 16 + g;
        #pragma unroll
        for (int j = 0; j < 4; j++) {
            const int col = (wn * 4 + j) * 8 + 2 * t4;
            float2 lo = make_float2(acc[i][j].x + b0[j], acc[i][j].y + b1[j]);
            float2 hi = make_float2(acc[i][j].z + b0[j], acc[i][j].w + b1[j]);
            *(float2*)(dst + (size_t)row0 * FF + col)       = lo;
            *(float2*)(dst + (size_t)(row0 + 8) * FF + col) = hi;
        }
    }

    if (r < 12) {
        const int inst = b * 12 + r;
        #pragma unroll
        for (int j = 0; j < 4; j++) {
            float s0 = 0.f, s1 = 0.f;
            #pragma unroll
            for (int i = 0; i < 2; i++) {
                s0 += acc[i][j].x + acc[i][j].z;
                s1 += acc[i][j].y + acc[i][j].w;
            }
            #pragma unroll
            for (int off = 16; off >= 4; off >>= 1) {
                s0 += __shfl_down_sync(0xffffffffu, s0, off);
                s1 += __shfl_down_sync(0xffffffffu, s1, off);
            }
            if (lane < 4) {
                const int col = (wn * 4 + j) * 8 + 2 * lane;
                atomicAdd(&g_Htot[inst * FF + col],     s0 + 32.f * bv[col]);
                atomicAdd(&g_Htot[inst * FF + col + 1], s1 + 32.f * bv[col + 1]);
            }
        }
    }
}

// ==================== attention e-vectors (esrc incl. bias) =====================
__global__ __launch_bounds__(256) void evec_kernel(
    const float* __restrict__ att_w,  const float* __restrict__ att_b,
    const float* __restrict__ fwd_aw, const float* __restrict__ fwd_ab,
    const float* __restrict__ bwd_aw, const float* __restrict__ bwd_ab)
{
    const int op = blockIdx.y, b = blockIdx.z;
    const int warp = threadIdx.x >> 5, lane = threadIdx.x & 31;
    const int row = blockIdx.x * 8 + warp;
    const int hsel = (op < 6) ? op : 5;
    const float* hrow = g_H + (((size_t)b * 12 + hsel) * NN + row) * FF;
    const float* w; float ab;
    if (op < 6)      { w = att_w  + op * 2 * FF;       ab = att_b[op]; }
    else if (op < 9) { w = fwd_aw + (op - 6) * 2 * FF; ab = fwd_ab[op - 6]; }
    else             { w = bwd_aw + (op - 9) * 2 * FF; ab = bwd_ab[op - 9]; }
    float s1 = 0.f, s2 = 0.f;
    #pragma unroll
    for (int q = 0; q < 4; q++) {
        float hv = hrow[lane + 32 * q];
        s1 += hv * w[lane + 32 * q];
        s2 += hv * w[FF + lane + 32 * q];
    }
    #pragma unroll
    for (int off = 16; off > 0; off >>= 1) {
        s1 += __shfl_down_sync(0xffffffffu, s1, off);
        s2 += __shfl_down_sync(0xffffffffu, s2, off);
    }
    if (lane == 0) {
        g_esrc[(b * 12 + op) * NN + row] = s1 + ab;
        g_edst[(b * 12 + op) * NN + row] = s2;
    }
}

// ============== dense-tile MMA aggregation (flash-attention style) ==============
// out_row = scale*(Htot + A_w @ H) / (1024 + A_w @ ones), A_w built per tile in
// bf16 MMA-fragment layout from the rank-1 e decomposition + bit masks.
#define AGG_SMEM ((8192 + 8192 + 512 + 128 + 128) * 4)

__device__ __forceinline__ void mma_bf16(float4& d, const uint4 a, const uint2 b)
{
    asm volatile(
        "mma.sync.aligned.m16n8k16.row.col.f32.bf16.bf16.f32 "
        "{%0,%1,%2,%3}, {%4,%5,%6,%7}, {%8,%9}, {%0,%1,%2,%3};"
        : "+f"(d.x), "+f"(d.y), "+f"(d.z), "+f"(d.w)
        : "r"(a.x), "r"(a.y), "r"(a.z), "r"(a.w), "r"(b.x), "r"(b.y));
}

__global__ __launch_bounds__(512, 2) void agg_kernel()
{
    extern __shared__ uint32_t sm[];
    uint32_t* Aw     = sm;           // [mt8][kt8][lane32][reg4] bf16x2
    uint32_t* Hb     = sm + 8192;    // [nt16][kt8][lane32][reg2] bf16x2
    uint32_t* mw_s   = sm + 16384;   // [128 rows][4 words]
    float*    esrc_s = (float*)(sm + 16896);   // [128]
    float*    edst_s = esrc_s + 128;           // [128]

    const int rb = blockIdx.x, op = blockIdx.y, b = blockIdx.z;
    const int inst = b * 12 + op;
    const int tid = threadIdx.x;
    const float* Hm = g_H + (size_t)inst * NN * FF;

    const uint32_t* rowbits = nullptr;
    const uint32_t* dwords = nullptr;
    float scale = 1.0f;
    if (op < 3)      rowbits = g_rowbits + (((size_t)(b * 6 + op)) * NN) * 32;
    else if (op < 6) dwords = g_dbits + (b * 3 + (op - 3)) * 32;
    else if (op < 9) { rowbits = g_rowbits + (((size_t)(b * 6 + op - 3)) * NN) * 32; scale = 0.5f; }
    else             { rowbits = g_bitsT + (((size_t)(b * 3 + op - 9)) * NN) * 32;   scale = 0.5f; }

    // esrc for this row block (fixed across chunks)
    if (tid < 128) esrc_s[tid] = g_esrc[inst * NN + rb * 128 + tid];

    const int warp = tid >> 5, lane = tid & 31;
    const int wm = warp >> 2, wn = warp & 3;          // warp tile 32 rows x 32 feats
    const uint2 ones = make_uint2(0x3F803F80u, 0x3F803F80u);

    float4 acc[2][4]; float4 accws[2];
    #pragma unroll
    for (int i = 0; i < 2; i++) {
        accws[i] = make_float4(0.f, 0.f, 0.f, 0.f);
        #pragma unroll
        for (int j = 0; j < 4; j++) acc[i][j] = make_float4(0.f, 0.f, 0.f, 0.f);
    }

    for (int c = 0; c < 8; c++) {
        const int cb = c * 128, cw = cb >> 5;
        __syncthreads();   // previous MMA reads done before refill

        // ---- preload mask words (128 rows x 4 words) + edst chunk ----
        {
            const int rl = tid >> 2, wq = tid & 3;
            uint32_t w;
            if (rowbits) {
                w = __ldg(rowbits + (size_t)(rb * 128 + rl) * 32 + cw + wq);
            } else {
                const int row = rb * 128 + rl;
                uint32_t di = (__ldg(dwords + (row >> 5)) >> (row & 31)) & 1u;
                w = di ? __ldg(dwords + cw + wq) : 0u;
            }
            mw_s[tid] = w;
            if (tid < 128) edst_s[tid] = g_edst[inst * NN + cb + tid];
        }
        // ---- H chunk -> B fragments (bf16) ----
        #pragma unroll
        for (int it = 0; it < 4; it++) {
            const int q = tid + it * 512;
            const int f4 = q & 31, jp = q >> 5;
            const int j = jp * 2;
            const int kt = j >> 4, rg = (j >> 3) & 1, tt = (j >> 1) & 3;
            float4 va = *(const float4*)(Hm + (size_t)(cb + j) * FF + f4 * 4);
            float4 vb = *(const float4*)(Hm + (size_t)(cb + j + 1) * FF + f4 * 4);
            #pragma unroll
            for (int u = 0; u < 4; u++) {
                const int f = f4 * 4 + u;
                const int nt = f >> 3, gg = f & 7;
                const int lane2 = gg * 4 + tt;
                Hb[(((nt * 8 + kt) * 32 + lane2) * 2) + rg] =
                    pack_bf16x2((&va.x)[u], (&vb.x)[u]);
            }
        }
        __syncthreads();   // masks + edst + Hb visible to all
        // ---- A_w tile -> A fragments (bf16) ----
        #pragma unroll
        for (int it = 0; it < 16; it++) {
            const int s = tid + it * 512;
            const int reg = s & 3, lane2 = (s >> 2) & 31;
            const int kt = (s >> 7) & 7, mt = s >> 10;
            const int g = lane2 >> 2, tt = lane2 & 3;
            const int m = mt * 16 + g + (reg & 1) * 8;
            const int k = kt * 16 + tt * 2 + (reg & 2) * 4;
            const uint32_t bits = (mw_s[m * 4 + (k >> 5)] >> (k & 31)) & 3u;
            const float es = esrc_s[m];
            float2 ed = *(const float2*)(edst_s + k);
            float e0 = es + ed.x, e1 = es + ed.y;
            e0 = fmaxf(e0, 0.01f * e0);
            e1 = fmaxf(e1, 0.01f * e1);
            float w0 = (bits & 1u) ? (__expf(e0) - 1.0f) : 0.f;
            float w1 = (bits & 2u) ? (__expf(e1) - 1.0f) : 0.f;
            Aw[s] = pack_bf16x2(w0, w1);
        }
        __syncthreads();

        // ---- MMAs ----
        #pragma unroll
        for (int kt = 0; kt < 8; kt++) {
            uint4 a[2]; uint2 bb[4];
            #pragma unroll
            for (int i = 0; i < 2; i++)
                a[i] = *(const uint4*)(Aw + (((wm * 2 + i) * 8 + kt) * 32 + lane) * 4);
            #pragma unroll
            for (int j = 0; j < 4; j++)
                bb[j] = *(const uint2*)(Hb + (((wn * 4 + j) * 8 + kt) * 32 + lane) * 2);
            #pragma unroll
            for (int i = 0; i < 2; i++) {
                #pragma unroll
                for (int j = 0; j < 4; j++)
                    mma_bf16(acc[i][j], a[i], bb[j]);
                mma_bf16(accws[i], a[i], ones);
            }
        }
    }

    // ---- epilogue: (Htot + U) * scale / (1024 + Wsum) ----
    const int g = lane >> 2, t4 = lane & 3;
    float* part = g_part[op] + ((size_t)b * NN) * FF;
    #pragma unroll
    for (int i = 0; i < 2; i++) {
        const float inv0 = scale / (1024.0f + accws[i].x);
        const float inv1 = scale / (1024.0f + accws[i].z);
        const int m0 = rb * 128 + (wm * 2 + i) * 16 + g;
        #pragma unroll
        for (int j = 0; j < 4; j++) {
            const int f = (wn * 4 + j) * 8 + t4 * 2;
            const float2 ht = *(const float2*)(g_Htot + inst * FF + f);
            float2 lo = make_float2((ht.x + acc[i][j].x) * inv0,
                                    (ht.y + acc[i][j].y) * inv0);
            float2 hi = make_float2((ht.x + acc[i][j].z) * inv1,
                                    (ht.y + acc[i][j].w) * inv1);
            *(float2*)(part + (size_t)m0 * FF + f)       = lo;
            *(float2*)(part + (size_t)(m0 + 8) * FF + f) = hi;
        }
    }
}

// =========================== final reduce + ReLU ================================
__global__ __launch_bounds__(256) void reduce_kernel(float* __restrict__ out)
{
    const int i = blockIdx.x * blockDim.x + threadIdx.x;   // float4 index
    float4 v = ((const float4*)g_outacc)[i];
    #pragma unroll
    for (int op = 0; op < 12; op++) {
        float4 p = ((const float4*)(g_part[op]))[i];
        v.x += p.x; v.y += p.y; v.z += p.z; v.w += p.w;
    }
    v.x = fmaxf(v.x, 0.f); v.y = fmaxf(v.y, 0.f);
    v.z = fmaxf(v.z, 0.f); v.w = fmaxf(v.w, 0.f);
    ((float4*)out)[i] = v;
}

// ================================================================================
extern "C" void kernel_launch(void* const* d_in, const int* in_sizes, int n_in,
                              void* d_out, int out_size)
{
    const float* batch_x    = (const float*)d_in[0];
    const float* batch_adjs = (const float*)d_in[1];
    const float* fc_w       = (const float*)d_in[2];
    const float* fc_b       = (const float*)d_in[3];
    const float* att_w      = (const float*)d_in[4];
    const float* att_b      = (const float*)d_in[5];
    const float* fwd_fc_w   = (const float*)d_in[6];
    const float* fwd_fc_b   = (const float*)d_in[7];
    const float* fwd_att_w  = (const float*)d_in[8];
    const float* fwd_att_b  = (const float*)d_in[9];
    const float* bwd_fc_w   = (const float*)d_in[10];
    const float* bwd_fc_b   = (const float*)d_in[11];
    const float* bwd_att_w  = (const float*)d_in[12];
    const float* bwd_att_b  = (const float*)d_in[13];
    const float* self_w     = (const float*)d_in[14];
    const float* self_b     = (const float*)d_in[15];
    const float* bias       = (const float*)d_in[16];
    float* out = (float*)d_out;

    static bool attr_done = false;
    if (!attr_done) {
        cudaFuncSetAttribute(agg_kernel, cudaFuncAttributeMaxDynamicSharedMemorySize, AGG_SMEM);
        cudaFuncSetAttribute(gemm_kernel, cudaFuncAttributeMaxDynamicSharedMemorySize, GEMM_SMEM);
        attr_done = true;
    }

    bitpack_kernel<<<dim3(32, 7, 8), 256>>>(batch_adjs);                  // launch 0
    gemm_kernel<<<dim3(8, 13, 8), 512, GEMM_SMEM>>>(batch_x, fc_w, fc_b, // launch 1
                                                    fwd_fc_w, fwd_fc_b,
                                                    bwd_fc_w, bwd_fc_b,
                                                    self_w, self_b, bias);
    evec_kernel<<<dim3(128, 12, 8), 256>>>(att_w, att_b, fwd_att_w,       // launch 2
                                           fwd_att_b, bwd_att_w, bwd_att_b);
    agg_kernel<<<dim3(8, 12, 8), 512, AGG_SMEM>>>();                      // launch 3 (ncu target)
    reduce_kernel<<<1024, 256>>>(out);                                    // launch 4
}

// round 7
// speedup vs baseline: 1.4078x; 1.4078x over previous
#include <cuda_runtime.h>
#include <cuda_bf16.h>
#include <stdint.h>

#define BATCH 8
#define NN    1024
#define FF    128

// ---------------- scratch (no allocations allowed -> __device__ globals) --------
__device__ float    g_H[(size_t)BATCH * 12 * NN * FF];     // 48 MB
__device__ uint32_t g_Hbf[(size_t)BATCH * 12 * 8 * 8192];  // 25 MB bf16 B-fragments
__device__ float    g_outacc[(size_t)BATCH * NN * FF];     // 4 MB (self contribution)
__device__ float    g_part[12][(size_t)BATCH * NN * FF];   // 48 MB per-op partials
__device__ float    g_esrc[BATCH * 12 * NN];
__device__ float    g_edst[BATCH * 12 * NN];
__device__ float    g_Htot[BATCH * 12 * FF];
__device__ uint32_t g_rowbits[(size_t)BATCH * 6 * NN * 32];  // rel 0-2, 6-8 row masks
__device__ uint32_t g_bitsT[(size_t)BATCH * 3 * NN * 32];    // rel 6-8 transposed masks
__device__ uint32_t g_dbits[BATCH * 3 * 32];                 // diag masks (rel 3-5)

// pack two fp32 into bf16x2 word (lo -> low half, hi -> high half)
__device__ __forceinline__ uint32_t pack_bf16x2(float lo, float hi)
{
    uint32_t r;
    asm("cvt.rn.bf16x2.f32 %0, %1, %2;" : "=r"(r) : "f"(hi), "f"(lo));
    return r;
}

// =========== fused bitpack: row masks, transposed masks, diag, Htot zero ========
__global__ __launch_bounds__(256) void bitpack_kernel(const float* __restrict__ adjs)
{
    const int slab = blockIdx.x, y = blockIdx.y, b = blockIdx.z;
    const int warp = threadIdx.x >> 5, lane = threadIdx.x & 31;

    if (y == 6) {
        if (slab < 3) {                       // diag masks for rel 3..5
            #pragma unroll
            for (int rr = 0; rr < 4; rr++) {
                const int i = rr * 256 + threadIdx.x;
                float v = adjs[(((size_t)(b * 9 + 3 + slab)) * NN + i) * NN + i];
                unsigned m = __ballot_sync(0xffffffffu, v > 0.f);
                if (lane == 0) g_dbits[(b * 3 + slab) * 32 + (i >> 5)] = m;
            }
        } else if (slab == 3 && b == 0) {     // zero Htot (before gemm's atomics)
            for (int t = threadIdx.x; t < BATCH * 12 * FF; t += 256) g_Htot[t] = 0.f;
        }
        return;
    }

    const bool doT = (y >= 3);
    const int rel = doT ? (y + 3) : y;        // y 0-2 -> rel 0-2 ; y 3-5 -> rel 6-8
    __shared__ uint32_t sw[32 * 32];

    #pragma unroll
    for (int rr = 0; rr < 4; rr++) {
        const int row = slab * 32 + warp * 4 + rr;
        const float* rp = adjs + (((size_t)(b * 9 + rel)) * NN + row) * NN;
        uint32_t myw = 0;
        #pragma unroll 4
        for (int it = 0; it < 32; it++) {
            float v = rp[it * 32 + lane];
            unsigned mm = __ballot_sync(0xffffffffu, v > 0.f);
            if (lane == it) myw = mm;
        }
        g_rowbits[(((size_t)(b * 6 + y)) * NN + row) * 32 + lane] = myw;
        if (doT) sw[(warp * 4 + rr) * 32 + lane] = myw;
    }
    if (doT) {
        __syncthreads();
        for (int c = threadIdx.x; c < NN; c += 256) {
            const int word = c >> 5, bit = c & 31;
            uint32_t t = 0;
            #pragma unroll
            for (int r = 0; r < 32; r++)
                t |= ((sw[r * 32 + word] >> bit) & 1u) << r;
            g_bitsT[(((size_t)(b * 3 + (y - 3))) * NN + c) * 32 + slab] = t;
        }
    }
}

// =============================== tf32 GEMM ======================================
// Also computes Htot (col sums) and the esrc/edst attention vectors in-epilogue.
__device__ __forceinline__ uint32_t f2tf32(float f)
{
    uint32_t r;
    asm("cvt.rna.tf32.f32 %0, %1;" : "=r"(r) : "f"(f));
    return r;
}

__device__ __forceinline__ void mma_tf32(float4& d, const uint4 a, const uint2 b)
{
    asm volatile(
        "mma.sync.aligned.m16n8k8.row.col.f32.tf32.tf32.f32 "
        "{%0,%1,%2,%3}, {%4,%5,%6,%7}, {%8,%9}, {%0,%1,%2,%3};"
        : "+f"(d.x), "+f"(d.y), "+f"(d.z), "+f"(d.w)
        : "r"(a.x), "r"(a.y), "r"(a.z), "r"(a.w), "r"(b.x), "r"(b.y));
}

#define GEMM_SMEM (32768 * 4)

__global__ __launch_bounds__(512) void gemm_kernel(
    const float* __restrict__ x,
    const float* __restrict__ fc_w,  const float* __restrict__ fc_b,
    const float* __restrict__ fwd_w, const float* __restrict__ fwd_b,
    const float* __restrict__ bwd_w, const float* __restrict__ bwd_b,
    const float* __restrict__ self_w, const float* __restrict__ self_b,
    const float* __restrict__ bias,
    const float* __restrict__ att_w,  const float* __restrict__ att_b,
    const float* __restrict__ fwd_aw, const float* __restrict__ fwd_ab,
    const float* __restrict__ bwd_aw, const float* __restrict__ bwd_ab)
{
    extern __shared__ uint32_t sm[];
    uint32_t* As = sm;
    uint32_t* Ws = sm + 16384;

    const int rb = blockIdx.x, r = blockIdx.y, b = blockIdx.z;
    const int tid = threadIdx.x;

    const float* X = x + (size_t)b * NN * FF + (size_t)rb * 128 * FF;
    const float* Wp; const float* bv; const float* bv2 = nullptr; float* dst;
    if (r < 6)       { Wp = fc_w  + r * FF * FF;       bv = fc_b  + r * FF;
                       dst = g_H + ((size_t)(b * 12 + r)) * NN * FF; }
    else if (r < 9)  { Wp = fwd_w + (r - 6) * FF * FF; bv = fwd_b + (r - 6) * FF;
                       dst = g_H + ((size_t)(b * 12 + r)) * NN * FF; }
    else if (r < 12) { Wp = bwd_w + (r - 9) * FF * FF; bv = bwd_b + (r - 9) * FF;
                       dst = g_H + ((size_t)(b * 12 + r)) * NN * FF; }
    else             { Wp = self_w; bv = self_b; bv2 = bias;
                       dst = g_outacc + (size_t)b * NN * FF; }

    for (int t = tid; t < 4096; t += 512) {
        const int row = t >> 5;
        const int c = (t & 31) << 2;
        float4 v = *(const float4*)(X + (size_t)row * FF + c);
        const int m = row >> 4, lr = row & 15;
        const int s = c >> 3;
        const int reg = (lr >> 3) + ((c & 4) ? 2 : 0);
        uint32_t* base = As + (((m << 4) + s) << 7) + (((lr & 7) << 2) << 2) + reg;
        base[0]  = f2tf32(v.x);
        base[4]  = f2tf32(v.y);
        base[8]  = f2tf32(v.z);
        base[12] = f2tf32(v.w);
    }
    for (int t = tid; t < 4096; t += 512) {
        const int n = t >> 5;
        const int k = (t & 31) << 2;
        float4 v = *(const float4*)(Wp + (size_t)n * FF + k);
        const int nt = n >> 3;
        const int s = k >> 3;
        const int reg = (k & 4) ? 1 : 0;
        uint32_t* base = Ws + (((nt << 4) + s) << 6) + (((n & 7) << 2) << 1) + reg;
        base[0] = f2tf32(v.x);
        base[2] = f2tf32(v.y);
        base[4] = f2tf32(v.z);
        base[6] = f2tf32(v.w);
    }
    __syncthreads();

    const int warp = tid >> 5, lane = tid & 31;
    const int wm = warp >> 2, wn = warp & 3;

    float4 acc[2][4];
    #pragma unroll
    for (int i = 0; i < 2; i++)
        #pragma unroll
        for (int j = 0; j < 4; j++) acc[i][j] = make_float4(0.f, 0.f, 0.f, 0.f);

    #pragma unroll
    for (int s = 0; s < 16; s++) {
        uint4 a[2]; uint2 bb[4];
        #pragma unroll
        for (int i = 0; i < 2; i++)
            a[i] = *(const uint4*)(As + ((((wm * 2 + i) << 4) + s) << 7) + (lane << 2));
        #pragma unroll
        for (int j = 0; j < 4; j++)
            bb[j] = *(const uint2*)(Ws + ((((wn * 4 + j) << 4) + s) << 6) + (lane << 1));
        #pragma unroll
        for (int i = 0; i < 2; i++)
            #pragma unroll
            for (int j = 0; j < 4; j++)
                mma_tf32(acc[i][j], a[i], bb[j]);
    }

    const int g = lane >> 2, t4 = lane & 3;
    float b0[4], b1[4];
    #pragma unroll
    for (int j = 0; j < 4; j++) {
        const int col = (wn * 4 + j) * 8 + 2 * t4;
        b0[j] = bv[col];     b1[j] = bv[col + 1];
        if (bv2) { b0[j] += bv2[col]; b1[j] += bv2[col + 1]; }
    }
    #pragma unroll
    for (int i = 0; i < 2; i++) {
        const int row0 = rb * 128 + (wm * 2 + i) * 16 + g;
        #pragma unroll
        for (int j = 0; j < 4; j++) {
            const int col = (wn * 4 + j) * 8 + 2 * t4;
            float2 lo = make_float2(acc[i][j].x + b0[j], acc[i][j].y + b1[j]);
            float2 hi = make_float2(acc[i][j].z + b0[j], acc[i][j].w + b1[j]);
            *(float2*)(dst + (size_t)row0 * FF + col)       = lo;
            *(float2*)(dst + (size_t)(row0 + 8) * FF + col) = hi;
        }
    }

    if (r < 12) {
        const int inst = b * 12 + r;
        #pragma unroll
        for (int j = 0; j < 4; j++) {
            float s0 = 0.f, s1 = 0.f;
            #pragma unroll
            for (int i = 0; i < 2; i++) {
                s0 += acc[i][j].x + acc[i][j].z;
                s1 += acc[i][j].y + acc[i][j].w;
            }
            #pragma unroll
            for (int off = 16; off >= 4; off >>= 1) {
                s0 += __shfl_down_sync(0xffffffffu, s0, off);
                s1 += __shfl_down_sync(0xffffffffu, s1, off);
            }
            if (lane < 4) {
                const int col = (wn * 4 + j) * 8 + 2 * lane;
                atomicAdd(&g_Htot[inst * FF + col],     s0 + 32.f * bv[col]);
                atomicAdd(&g_Htot[inst * FF + col + 1], s1 + 32.f * bv[col + 1]);
            }
        }
    }

    // ---- fused attention e-vectors (esrc/edst) for r<6; r==5 also serves ops 6-11
    if (r < 6) {
        float* es_s = (float*)sm;         // reuse As region
        float* ed_s = ((float*)sm) + 128;
        const int nsets = (r == 5) ? 7 : 1;
        for (int set = 0; set < nsets; set++) {
            const int opx = (set == 0) ? r : 5 + set;
            const float* w; float ab;
            if (opx < 6)      { w = att_w  + opx * 2 * FF;       ab = att_b[opx]; }
            else if (opx < 9) { w = fwd_aw + (opx - 6) * 2 * FF; ab = fwd_ab[opx - 6]; }
            else              { w = bwd_aw + (opx - 9) * 2 * FF; ab = bwd_ab[opx - 9]; }
            // bias-dot constants (warp-redundant): C1 = ab + sum bv*w1, C2 = sum bv*w2
            float c1 = 0.f, c2 = 0.f;
            #pragma unroll
            for (int q = 0; q < 4; q++) {
                float bvv = bv[lane + 32 * q];
                c1 += bvv * w[lane + 32 * q];
                c2 += bvv * w[FF + lane + 32 * q];
            }
            #pragma unroll
            for (int off = 16; off > 0; off >>= 1) {
                c1 += __shfl_xor_sync(0xffffffffu, c1, off);
                c2 += __shfl_xor_sync(0xffffffffu, c2, off);
            }
            c1 += ab;
            __syncthreads();                       // smem safe to overwrite
            if (tid < 128) { es_s[tid] = 0.f; ed_s[tid] = 0.f; }
            __syncthreads();
            #pragma unroll
            for (int i = 0; i < 2; i++) {
                const int rl = (wm * 2 + i) * 16 + g;
                float p1a = 0.f, p2a = 0.f, p1b = 0.f, p2b = 0.f;
                #pragma unroll
                for (int j = 0; j < 4; j++) {
                    const int col = (wn * 4 + j) * 8 + 2 * t4;
                    const float w1a = w[col],      w1b = w[col + 1];
                    const float w2a = w[FF + col], w2b = w[FF + col + 1];
                    p1a += acc[i][j].x * w1a + acc[i][j].y * w1b;
                    p2a += acc[i][j].x * w2a + acc[i][j].y * w2b;
                    p1b += acc[i][j].z * w1a + acc[i][j].w * w1b;
                    p2b += acc[i][j].z * w2a + acc[i][j].w * w2b;
                }
                atomicAdd(&es_s[rl], p1a);     atomicAdd(&ed_s[rl], p2a);
                atomicAdd(&es_s[rl + 8], p1b); atomicAdd(&ed_s[rl + 8], p2b);
            }
            __syncthreads();
            if (tid < 128) {
                g_esrc[(b * 12 + opx) * NN + rb * 128 + tid] = es_s[tid] + c1;
                g_edst[(b * 12 + opx) * NN + rb * 128 + tid] = ed_s[tid] + c2;
            }
        }
    }
}

// ============ H -> bf16 MMA-B-fragment conversion (once per instance) ===========
__global__ __launch_bounds__(256) void hconv_kernel()
{
    __shared__ uint32_t sm[64 * 140];     // row-pair major, pad 140 -> conflict-free
    const int c = blockIdx.x, op = blockIdx.y, b = blockIdx.z;
    const int inst = b * 12 + op;
    const int tid = threadIdx.x, warp = tid >> 5, lane = tid & 31;
    const float* Hm = g_H + ((size_t)inst * NN + c * 128) * FF;

    #pragma unroll
    for (int rep = 0; rep < 8; rep++) {
        const int w = warp * 8 + rep;     // row pair 0..63
        float4 va = *(const float4*)(Hm + (size_t)(2 * w) * FF + lane * 4);
        float4 vb = *(const float4*)(Hm + (size_t)(2 * w + 1) * FF + lane * 4);
        uint4 o;
        o.x = pack_bf16x2(va.x, vb.x);
        o.y = pack_bf16x2(va.y, vb.y);
        o.z = pack_bf16x2(va.z, vb.z);
        o.w = pack_bf16x2(va.w, vb.w);
        *(uint4*)(sm + w * 140 + lane * 4) = o;
    }
    __syncthreads();

    uint32_t* dst = g_Hbf + ((size_t)inst * 8 + c) * 8192;
    #pragma unroll
    for (int it = 0; it < 32; it++) {
        const int o = it * 256 + tid;
        const int rg = o & 1, l2 = (o >> 1) & 31, kt = (o >> 6) & 7, nt = o >> 9;
        const int tt = l2 & 3, g = l2 >> 2;
        dst[o] = sm[(kt * 8 + rg * 4 + tt) * 140 + nt * 8 + g];
    }
}

// ============== dense-tile MMA aggregation (flash-attention style) ==============
// out_row = scale*(Htot + A_w @ H) / (1024 + A_w @ ones); A_w built in smem in
// bf16 A-fragment layout; H B-fragments streamed from gmem (L2-resident).
__device__ __forceinline__ void mma_bf16(float4& d, const uint4 a, const uint2 b)
{
    asm volatile(
        "mma.sync.aligned.m16n8k16.row.col.f32.bf16.bf16.f32 "
        "{%0,%1,%2,%3}, {%4,%5,%6,%7}, {%8,%9}, {%0,%1,%2,%3};"
        : "+f"(d.x), "+f"(d.y), "+f"(d.z), "+f"(d.w)
        : "r"(a.x), "r"(a.y), "r"(a.z), "r"(a.w), "r"(b.x), "r"(b.y));
}

__global__ __launch_bounds__(512, 2) void agg_kernel()
{
    __shared__ uint32_t Aw[8192];          // [mt8][kt8][lane32][reg4] bf16x2
    __shared__ uint32_t mw_s[512];         // [128 rows][4 words]
    __shared__ float    esrc_s[128];
    __shared__ float    edst_s[128];

    const int rb = blockIdx.x, op = blockIdx.y, b = blockIdx.z;
    const int inst = b * 12 + op;
    const int tid = threadIdx.x;

    const uint32_t* rowbits = nullptr;
    const uint32_t* dwords = nullptr;
    float scale = 1.0f;
    if (op < 3)      rowbits = g_rowbits + (((size_t)(b * 6 + op)) * NN) * 32;
    else if (op < 6) dwords = g_dbits + (b * 3 + (op - 3)) * 32;
    else if (op < 9) { rowbits = g_rowbits + (((size_t)(b * 6 + op - 3)) * NN) * 32; scale = 0.5f; }
    else             { rowbits = g_bitsT + (((size_t)(b * 3 + op - 9)) * NN) * 32;   scale = 0.5f; }

    if (tid < 128) esrc_s[tid] = g_esrc[inst * NN + rb * 128 + tid];

    const int warp = tid >> 5, lane = tid & 31;
    const int wm = warp >> 2, wn = warp & 3;          // warp tile 32 rows x 32 feats
    const uint2 ones = make_uint2(0x3F803F80u, 0x3F803F80u);
    const uint32_t* Bg0 = g_Hbf + (size_t)inst * 8 * 8192;

    float4 acc[2][4]; float4 accws[2];
    #pragma unroll
    for (int i = 0; i < 2; i++) {
        accws[i] = make_float4(0.f, 0.f, 0.f, 0.f);
        #pragma unroll
        for (int j = 0; j < 4; j++) acc[i][j] = make_float4(0.f, 0.f, 0.f, 0.f);
    }

    for (int c = 0; c < 8; c++) {
        const int cb = c * 128, cw = cb >> 5;

        // ---- mask words (128 rows x 4 words) + edst chunk ----
        {
            const int rl = tid >> 2, wq = tid & 3;
            uint32_t w;
            if (rowbits) {
                w = __ldg(rowbits + (size_t)(rb * 128 + rl) * 32 + cw + wq);
            } else {
                const int row = rb * 128 + rl;
                uint32_t di = (__ldg(dwords + (row >> 5)) >> (row & 31)) & 1u;
                w = di ? __ldg(dwords + cw + wq) : 0u;
            }
            mw_s[tid] = w;
            if (tid < 128) edst_s[tid] = g_edst[inst * NN + cb + tid];
        }
        __syncthreads();   // masks/edst visible; prev MMA done (prog order)

        // ---- A_w tile -> A fragments (bf16), conflict-free stores ----
        #pragma unroll
        for (int it = 0; it < 16; it++) {
            const int s = tid + it * 512;
            const int reg = s & 3, lane2 = (s >> 2) & 31;
            const int kt = (s >> 7) & 7, mt = s >> 10;
            const int g = lane2 >> 2, tt = lane2 & 3;
            const int m = mt * 16 + g + (reg & 1) * 8;
            const int k = kt * 16 + tt * 2 + (reg & 2) * 4;
            const uint32_t bits = (mw_s[m * 4 + (k >> 5)] >> (k & 31)) & 3u;
            const float es = esrc_s[m];
            float2 ed = *(const float2*)(edst_s + k);
            float e0 = es + ed.x, e1 = es + ed.y;
            e0 = fmaxf(e0, 0.01f * e0);
            e1 = fmaxf(e1, 0.01f * e1);
            float w0 = (bits & 1u) ? (__expf(e0) - 1.0f) : 0.f;
            float w1 = (bits & 2u) ? (__expf(e1) - 1.0f) : 0.f;
            Aw[s] = pack_bf16x2(w0, w1);
        }
        __syncthreads();

        // ---- MMAs: A from smem, B from gmem (L2) ----
        const uint32_t* Bg = Bg0 + (size_t)c * 8192;
        #pragma unroll
        for (int kt = 0; kt < 8; kt++) {
            uint4 a[2]; uint2 bb[4];
            #pragma unroll
            for (int i = 0; i < 2; i++)
                a[i] = *(const uint4*)(Aw + (((wm * 2 + i) * 8 + kt) * 32 + lane) * 4);
            #pragma unroll
            for (int j = 0; j < 4; j++)
                bb[j] = *(const uint2*)(Bg + (((wn * 4 + j) * 8 + kt) * 32 + lane) * 2);
            #pragma unroll
            for (int i = 0; i < 2; i++) {
                #pragma unroll
                for (int j = 0; j < 4; j++)
                    mma_bf16(acc[i][j], a[i], bb[j]);
                mma_bf16(accws[i], a[i], ones);
            }
        }
    }

    // ---- epilogue: (Htot + U) * scale / (1024 + Wsum) ----
    const int g = lane >> 2, t4 = lane & 3;
    float* part = g_part[op] + ((size_t)b * NN) * FF;
    #pragma unroll
    for (int i = 0; i < 2; i++) {
        const float inv0 = scale / (1024.0f + accws[i].x);
        const float inv1 = scale / (1024.0f + accws[i].z);
        const int m0 = rb * 128 + (wm * 2 + i) * 16 + g;
        #pragma unroll
        for (int j = 0; j < 4; j++) {
            const int f = (wn * 4 + j) * 8 + t4 * 2;
            const float2 ht = *(const float2*)(g_Htot + inst * FF + f);
            float2 lo = make_float2((ht.x + acc[i][j].x) * inv0,
                                    (ht.y + acc[i][j].y) * inv0);
            float2 hi = make_float2((ht.x + acc[i][j].z) * inv1,
                                    (ht.y + acc[i][j].w) * inv1);
            *(float2*)(part + (size_t)m0 * FF + f)       = lo;
            *(float2*)(part + (size_t)(m0 + 8) * FF + f) = hi;
        }
    }
}

// =========================== final reduce + ReLU ================================
__global__ __launch_bounds__(256) void reduce_kernel(float* __restrict__ out)
{
    const int i = blockIdx.x * blockDim.x + threadIdx.x;   // float4 index
    float4 v = ((const float4*)g_outacc)[i];
    #pragma unroll
    for (int op = 0; op < 12; op++) {
        float4 p = ((const float4*)(g_part[op]))[i];
        v.x += p.x; v.y += p.y; v.z += p.z; v.w += p.w;
    }
    v.x = fmaxf(v.x, 0.f); v.y = fmaxf(v.y, 0.f);
    v.z = fmaxf(v.z, 0.f); v.w = fmaxf(v.w, 0.f);
    ((float4*)out)[i] = v;
}

// ================================================================================
extern "C" void kernel_launch(void* const* d_in, const int* in_sizes, int n_in,
                              void* d_out, int out_size)
{
    const float* batch_x    = (const float*)d_in[0];
    const float* batch_adjs = (const float*)d_in[1];
    const float* fc_w       = (const float*)d_in[2];
    const float* fc_b       = (const float*)d_in[3];
    const float* att_w      = (const float*)d_in[4];
    const float* att_b      = (const float*)d_in[5];
    const float* fwd_fc_w   = (const float*)d_in[6];
    const float* fwd_fc_b   = (const float*)d_in[7];
    const float* fwd_att_w  = (const float*)d_in[8];
    const float* fwd_att_b  = (const float*)d_in[9];
    const float* bwd_fc_w   = (const float*)d_in[10];
    const float* bwd_fc_b   = (const float*)d_in[11];
    const float* bwd_att_w  = (const float*)d_in[12];
    const float* bwd_att_b  = (const float*)d_in[13];
    const float* self_w     = (const float*)d_in[14];
    const float* self_b     = (const float*)d_in[15];
    const float* bias       = (const float*)d_in[16];
    float* out = (float*)d_out;

    static bool attr_done = false;
    if (!attr_done) {
        cudaFuncSetAttribute(gemm_kernel, cudaFuncAttributeMaxDynamicSharedMemorySize, GEMM_SMEM);
        attr_done = true;
    }

    bitpack_kernel<<<dim3(32, 7, 8), 256>>>(batch_adjs);                  // launch 0
    gemm_kernel<<<dim3(8, 13, 8), 512, GEMM_SMEM>>>(batch_x, fc_w, fc_b, // launch 1
                                                    fwd_fc_w, fwd_fc_b,
                                                    bwd_fc_w, bwd_fc_b,
                                                    self_w, self_b, bias,
                                                    att_w, att_b, fwd_att_w,
                                                    fwd_att_b, bwd_att_w, bwd_att_b);
    hconv_kernel<<<dim3(8, 12, 8), 256>>>();                              // launch 2
    agg_kernel<<<dim3(8, 12, 8), 512>>>();                                // launch 3 (ncu target)
    reduce_kernel<<<1024, 256>>>(out);                                    // launch 4
}

// round 12
// speedup vs baseline: 1.7447x; 1.2393x over previous
#include <cuda_runtime.h>
#include <cuda_bf16.h>
#include <stdint.h>

#define BATCH 8
#define NN    1024
#define FF    128

// ---------------- scratch (no allocations allowed -> __device__ globals) --------
__device__ float    g_H[(size_t)BATCH * 12 * NN * FF];     // 48 MB
__device__ uint32_t g_Hbf[(size_t)BATCH * 12 * 8 * 8192];  // 25 MB bf16 B-fragments
__device__ float    g_outacc[(size_t)BATCH * NN * FF];     // 4 MB (self contribution)
__device__ float    g_part[12][(size_t)BATCH * NN * FF];   // 48 MB per-op partials
__device__ float    g_esrc[BATCH * 12 * NN];
__device__ float    g_edst[BATCH * 12 * NN];
__device__ float    g_Htot[BATCH * 12 * FF];
__device__ uint32_t g_rowbits[(size_t)BATCH * 6 * NN * 32];  // rel 0-2, 6-8 row masks
__device__ uint32_t g_bitsT[(size_t)BATCH * 3 * NN * 32];    // rel 6-8 transposed masks
__device__ uint32_t g_dbits[BATCH * 3 * 32];                 // diag masks (rel 3-5)

// pack two fp32 into bf16x2 word (lo -> low half, hi -> high half)
__device__ __forceinline__ uint32_t pack_bf16x2(float lo, float hi)
{
    uint32_t r;
    asm("cvt.rn.bf16x2.f32 %0, %1, %2;" : "=r"(r) : "f"(hi), "f"(lo));
    return r;
}

// =========== fused bitpack: row masks, transposed masks, diag, Htot zero ========
__global__ __launch_bounds__(256) void bitpack_kernel(const float* __restrict__ adjs)
{
    const int slab = blockIdx.x, y = blockIdx.y, b = blockIdx.z;
    const int warp = threadIdx.x >> 5, lane = threadIdx.x & 31;

    if (y == 6) {
        if (slab < 3) {                       // diag masks for rel 3..5
            #pragma unroll
            for (int rr = 0; rr < 4; rr++) {
                const int i = rr * 256 + threadIdx.x;
                float v = adjs[(((size_t)(b * 9 + 3 + slab)) * NN + i) * NN + i];
                unsigned m = __ballot_sync(0xffffffffu, v > 0.f);
                if (lane == 0) g_dbits[(b * 3 + slab) * 32 + (i >> 5)] = m;
            }
        } else if (slab == 3 && b == 0) {     // zero Htot (before gemm's atomics)
            for (int t = threadIdx.x; t < BATCH * 12 * FF; t += 256) g_Htot[t] = 0.f;
        }
        return;
    }

    const bool doT = (y >= 3);
    const int rel = doT ? (y + 3) : y;        // y 0-2 -> rel 0-2 ; y 3-5 -> rel 6-8
    __shared__ uint32_t sw[32 * 32];

    #pragma unroll
    for (int rr = 0; rr < 4; rr++) {
        const int row = slab * 32 + warp * 4 + rr;
        const float* rp = adjs + (((size_t)(b * 9 + rel)) * NN + row) * NN;
        uint32_t myw = 0;
        #pragma unroll 4
        for (int it = 0; it < 32; it++) {
            float v = rp[it * 32 + lane];
            unsigned mm = __ballot_sync(0xffffffffu, v > 0.f);
            if (lane == it) myw = mm;
        }
        g_rowbits[(((size_t)(b * 6 + y)) * NN + row) * 32 + lane] = myw;
        if (doT) sw[(warp * 4 + rr) * 32 + lane] = myw;
    }
    if (doT) {
        __syncthreads();
        for (int c = threadIdx.x; c < NN; c += 256) {
            const int word = c >> 5, bit = c & 31;
            uint32_t t = 0;
            #pragma unroll
            for (int r = 0; r < 32; r++)
                t |= ((sw[r * 32 + word] >> bit) & 1u) << r;
            g_bitsT[(((size_t)(b * 3 + (y - 3))) * NN + c) * 32 + slab] = t;
        }
    }
}

// =============================== tf32 GEMM ======================================
// Also computes Htot (col sums) and the esrc/edst attention vectors in-epilogue.
__device__ __forceinline__ uint32_t f2tf32(float f)
{
    uint32_t r;
    asm("cvt.rna.tf32.f32 %0, %1;" : "=r"(r) : "f"(f));
    return r;
}

__device__ __forceinline__ void mma_tf32(float4& d, const uint4 a, const uint2 b)
{
    asm volatile(
        "mma.sync.aligned.m16n8k8.row.col.f32.tf32.tf32.f32 "
        "{%0,%1,%2,%3}, {%4,%5,%6,%7}, {%8,%9}, {%0,%1,%2,%3};"
        : "+f"(d.x), "+f"(d.y), "+f"(d.z), "+f"(d.w)
        : "r"(a.x), "r"(a.y), "r"(a.z), "r"(a.w), "r"(b.x), "r"(b.y));
}

#define GEMM_SMEM (32768 * 4)

__global__ __launch_bounds__(512) void gemm_kernel(
    const float* __restrict__ x,
    const float* __restrict__ fc_w,  const float* __restrict__ fc_b,
    const float* __restrict__ fwd_w, const float* __restrict__ fwd_b,
    const float* __restrict__ bwd_w, const float* __restrict__ bwd_b,
    const float* __restrict__ self_w, const float* __restrict__ self_b,
    const float* __restrict__ bias,
    const float* __restrict__ att_w,  const float* __restrict__ att_b,
    const float* __restrict__ fwd_aw, const float* __restrict__ fwd_ab,
    const float* __restrict__ bwd_aw, const float* __restrict__ bwd_ab)
{
    extern __shared__ uint32_t sm[];
    uint32_t* As = sm;
    uint32_t* Ws = sm + 16384;

    const int rb = blockIdx.x, r = blockIdx.y, b = blockIdx.z;
    const int tid = threadIdx.x;

    const float* X = x + (size_t)b * NN * FF + (size_t)rb * 128 * FF;
    const float* Wp; const float* bv; const float* bv2 = nullptr; float* dst;
    if (r < 6)       { Wp = fc_w  + r * FF * FF;       bv = fc_b  + r * FF;
                       dst = g_H + ((size_t)(b * 12 + r)) * NN * FF; }
    else if (r < 9)  { Wp = fwd_w + (r - 6) * FF * FF; bv = fwd_b + (r - 6) * FF;
                       dst = g_H + ((size_t)(b * 12 + r)) * NN * FF; }
    else if (r < 12) { Wp = bwd_w + (r - 9) * FF * FF; bv = bwd_b + (r - 9) * FF;
                       dst = g_H + ((size_t)(b * 12 + r)) * NN * FF; }
    else             { Wp = self_w; bv = self_b; bv2 = bias;
                       dst = g_outacc + (size_t)b * NN * FF; }

    for (int t = tid; t < 4096; t += 512) {
        const int row = t >> 5;
        const int c = (t & 31) << 2;
        float4 v = *(const float4*)(X + (size_t)row * FF + c);
        const int m = row >> 4, lr = row & 15;
        const int s = c >> 3;
        const int reg = (lr >> 3) + ((c & 4) ? 2 : 0);
        uint32_t* base = As + (((m << 4) + s) << 7) + (((lr & 7) << 2) << 2) + reg;
        base[0]  = f2tf32(v.x);
        base[4]  = f2tf32(v.y);
        base[8]  = f2tf32(v.z);
        base[12] = f2tf32(v.w);
    }
    for (int t = tid; t < 4096; t += 512) {
        const int n = t >> 5;
        const int k = (t & 31) << 2;
        float4 v = *(const float4*)(Wp + (size_t)n * FF + k);
        const int nt = n >> 3;
        const int s = k >> 3;
        const int reg = (k & 4) ? 1 : 0;
        uint32_t* base = Ws + (((nt << 4) + s) << 6) + (((n & 7) << 2) << 1) + reg;
        base[0] = f2tf32(v.x);
        base[2] = f2tf32(v.y);
        base[4] = f2tf32(v.z);
        base[6] = f2tf32(v.w);
    }
    __syncthreads();

    const int warp = tid >> 5, lane = tid & 31;
    const int wm = warp >> 2, wn = warp & 3;

    float4 acc[2][4];
    #pragma unroll
    for (int i = 0; i < 2; i++)
        #pragma unroll
        for (int j = 0; j < 4; j++) acc[i][j] = make_float4(0.f, 0.f, 0.f, 0.f);

    #pragma unroll
    for (int s = 0; s < 16; s++) {
        uint4 a[2]; uint2 bb[4];
        #pragma unroll
        for (int i = 0; i < 2; i++)
            a[i] = *(const uint4*)(As + ((((wm * 2 + i) << 4) + s) << 7) + (lane << 2));
        #pragma unroll
        for (int j = 0; j < 4; j++)
            bb[j] = *(const uint2*)(Ws + ((((wn * 4 + j) << 4) + s) << 6) + (lane << 1));
        #pragma unroll
        for (int i = 0; i < 2; i++)
            #pragma unroll
            for (int j = 0; j < 4; j++)
                mma_tf32(acc[i][j], a[i], bb[j]);
    }

    const int g = lane >> 2, t4 = lane & 3;
    float b0[4], b1[4];
    #pragma unroll
    for (int j = 0; j < 4; j++) {
        const int col = (wn * 4 + j) * 8 + 2 * t4;
        b0[j] = bv[col];     b1[j] = bv[col + 1];
        if (bv2) { b0[j] += bv2[col]; b1[j] += bv2[col + 1]; }
    }
    #pragma unroll
    for (int i = 0; i < 2; i++) {
        const int row0 = rb * 128 + (wm * 2 + i) * 16 + g;
        #pragma unroll
        for (int j = 0; j < 4; j++) {
            const int col = (wn * 4 + j) * 8 + 2 * t4;
            float2 lo = make_float2(acc[i][j].x + b0[j], acc[i][j].y + b1[j]);
            float2 hi = make_float2(acc[i][j].z + b0[j], acc[i][j].w + b1[j]);
            *(float2*)(dst + (size_t)row0 * FF + col)       = lo;
            *(float2*)(dst + (size_t)(row0 + 8) * FF + col) = hi;
        }
    }

    if (r < 12) {
        const int inst = b * 12 + r;
        #pragma unroll
        for (int j = 0; j < 4; j++) {
            float s0 = 0.f, s1 = 0.f;
            #pragma unroll
            for (int i = 0; i < 2; i++) {
                s0 += acc[i][j].x + acc[i][j].z;
                s1 += acc[i][j].y + acc[i][j].w;
            }
            #pragma unroll
            for (int off = 16; off >= 4; off >>= 1) {
                s0 += __shfl_down_sync(0xffffffffu, s0, off);
                s1 += __shfl_down_sync(0xffffffffu, s1, off);
            }
            if (lane < 4) {
                const int col = (wn * 4 + j) * 8 + 2 * lane;
                atomicAdd(&g_Htot[inst * FF + col],     s0 + 32.f * bv[col]);
                atomicAdd(&g_Htot[inst * FF + col + 1], s1 + 32.f * bv[col + 1]);
            }
        }
    }

    // ---- fused attention e-vectors (esrc/edst) for r<6; r==5 also serves ops 6-11
    if (r < 6) {
        float* es_s = (float*)sm;         // reuse As region
        float* ed_s = ((float*)sm) + 128;
        const int nsets = (r == 5) ? 7 : 1;
        for (int set = 0; set < nsets; set++) {
            const int opx = (set == 0) ? r : 5 + set;
            const float* w; float ab;
            if (opx < 6)      { w = att_w  + opx * 2 * FF;       ab = att_b[opx]; }
            else if (opx < 9) { w = fwd_aw + (opx - 6) * 2 * FF; ab = fwd_ab[opx - 6]; }
            else              { w = bwd_aw + (opx - 9) * 2 * FF; ab = bwd_ab[opx - 9]; }
            float c1 = 0.f, c2 = 0.f;
            #pragma unroll
            for (int q = 0; q < 4; q++) {
                float bvv = bv[lane + 32 * q];
                c1 += bvv * w[lane + 32 * q];
                c2 += bvv * w[FF + lane + 32 * q];
            }
            #pragma unroll
            for (int off = 16; off > 0; off >>= 1) {
                c1 += __shfl_xor_sync(0xffffffffu, c1, off);
                c2 += __shfl_xor_sync(0xffffffffu, c2, off);
            }
            c1 += ab;
            __syncthreads();
            if (tid < 128) { es_s[tid] = 0.f; ed_s[tid] = 0.f; }
            __syncthreads();
            #pragma unroll
            for (int i = 0; i < 2; i++) {
                const int rl = (wm * 2 + i) * 16 + g;
                float p1a = 0.f, p2a = 0.f, p1b = 0.f, p2b = 0.f;
                #pragma unroll
                for (int j = 0; j < 4; j++) {
                    const int col = (wn * 4 + j) * 8 + 2 * t4;
                    const float w1a = w[col],      w1b = w[col + 1];
                    const float w2a = w[FF + col], w2b = w[FF + col + 1];
                    p1a += acc[i][j].x * w1a + acc[i][j].y * w1b;
                    p2a += acc[i][j].x * w2a + acc[i][j].y * w2b;
                    p1b += acc[i][j].z * w1a + acc[i][j].w * w1b;
                    p2b += acc[i][j].z * w2a + acc[i][j].w * w2b;
                }
                atomicAdd(&es_s[rl], p1a);     atomicAdd(&ed_s[rl], p2a);
                atomicAdd(&es_s[rl + 8], p1b); atomicAdd(&ed_s[rl + 8], p2b);
            }
            __syncthreads();
            if (tid < 128) {
                g_esrc[(b * 12 + opx) * NN + rb * 128 + tid] = es_s[tid] + c1;
                g_edst[(b * 12 + opx) * NN + rb * 128 + tid] = ed_s[tid] + c2;
            }
        }
    }
}

// ============ H -> bf16 MMA-B-fragment conversion (once per instance) ===========
__global__ __launch_bounds__(256) void hconv_kernel()
{
    __shared__ uint32_t sm[64 * 140];     // row-pair major, pad 140 -> conflict-free
    const int c = blockIdx.x, op = blockIdx.y, b = blockIdx.z;
    const int inst = b * 12 + op;
    const int tid = threadIdx.x, warp = tid >> 5, lane = tid & 31;
    const float* Hm = g_H + ((size_t)inst * NN + c * 128) * FF;

    #pragma unroll
    for (int rep = 0; rep < 8; rep++) {
        const int w = warp * 8 + rep;     // row pair 0..63
        float4 va = *(const float4*)(Hm + (size_t)(2 * w) * FF + lane * 4);
        float4 vb = *(const float4*)(Hm + (size_t)(2 * w + 1) * FF + lane * 4);
        uint4 o;
        o.x = pack_bf16x2(va.x, vb.x);
        o.y = pack_bf16x2(va.y, vb.y);
        o.z = pack_bf16x2(va.z, vb.z);
        o.w = pack_bf16x2(va.w, vb.w);
        *(uint4*)(sm + w * 140 + lane * 4) = o;
    }
    __syncthreads();

    uint32_t* dst = g_Hbf + ((size_t)inst * 8 + c) * 8192;
    #pragma unroll
    for (int it = 0; it < 32; it++) {
        const int o = it * 256 + tid;
        const int rg = o & 1, l2 = (o >> 1) & 31, kt = (o >> 6) & 7, nt = o >> 9;
        const int tt = l2 & 3, g = l2 >> 2;
        dst[o] = sm[(kt * 8 + rg * 4 + tt) * 140 + nt * 8 + g];
    }
}

// ============== sparse-scatter MMA aggregation ==================================
// A_w tile zeroed then only ~5% edge entries scattered (bf16 STS.U16 into the
// MMA A-fragment layout). Wsum accumulated in fp32 registers (no ones-MMA).
__device__ __forceinline__ void mma_bf16(float4& d, const uint4 a, const uint2 b)
{
    asm volatile(
        "mma.sync.aligned.m16n8k16.row.col.f32.bf16.bf16.f32 "
        "{%0,%1,%2,%3}, {%4,%5,%6,%7}, {%8,%9}, {%0,%1,%2,%3};"
        : "+f"(d.x), "+f"(d.y), "+f"(d.z), "+f"(d.w)
        : "r"(a.x), "r"(a.y), "r"(a.z), "r"(a.w), "r"(b.x), "r"(b.y));
}

__global__ __launch_bounds__(512, 2) void agg_kernel()
{
    __shared__ uint32_t Aw[8192];          // [mt8][kt8][lane32][reg4] bf16x2
    __shared__ float    edst_s[128];
    __shared__ float    wsum_s[128];

    const int rb = blockIdx.x, op = blockIdx.y, b = blockIdx.z;
    const int inst = b * 12 + op;
    const int tid = threadIdx.x;
    const int rl = tid >> 2, wq = tid & 3;     // row-local 0..127, k-word 0..3

    const uint32_t* rowbits = nullptr;
    const uint32_t* dwords = nullptr;
    float scale = 1.0f;
    if (op < 3)      rowbits = g_rowbits + (((size_t)(b * 6 + op)) * NN) * 32;
    else if (op < 6) dwords = g_dbits + (b * 3 + (op - 3)) * 32;
    else if (op < 9) { rowbits = g_rowbits + (((size_t)(b * 6 + op - 3)) * NN) * 32; scale = 0.5f; }
    else             { rowbits = g_bitsT + (((size_t)(b * 3 + op - 9)) * NN) * 32;   scale = 0.5f; }

    const int warp = tid >> 5, lane = tid & 31;
    const int wm = warp >> 2, wn = warp & 3;          // warp tile 32 rows x 32 feats
    const uint32_t* Bg0 = g_Hbf + (size_t)inst * 8 * 8192;

    // per-thread scatter addressing constants (owned 16 Aw words, disjoint)
    const int mt = rl >> 4, gg = rl & 7, rb0 = (rl >> 3) & 1;
    const uint32_t byteBase = 4u * (uint32_t)(mt * 1024 + gg * 16 + rb0) + wq * 1024u;
    char* AwB = (char*)Aw;

    const float es = g_esrc[inst * NN + rb * 128 + rl];
    bool rowActive = true;
    if (dwords) {
        const int row = rb * 128 + rl;
        rowActive = ((__ldg(dwords + (row >> 5)) >> (row & 31)) & 1u) != 0;
    }

    if (tid < 128) wsum_s[tid] = 0.f;
    float wsum_local = 0.f;

    float4 acc[2][4];
    #pragma unroll
    for (int i = 0; i < 2; i++)
        #pragma unroll
        for (int j = 0; j < 4; j++) acc[i][j] = make_float4(0.f, 0.f, 0.f, 0.f);

    for (int c = 0; c < 8; c++) {
        const int cw = c * 4;
        __syncthreads();                   // prev MMA reads + wsum_s init done
        // cooperative zero of Aw (4 x STS.128 per thread)
        {
            const uint4 z = make_uint4(0u, 0u, 0u, 0u);
            #pragma unroll
            for (int t = 0; t < 4; t++)
                *(uint4*)(Aw + (tid + t * 512) * 4) = z;
        }
        // mask word (register) + edst chunk (smem)
        uint32_t mask;
        if (rowbits) mask = __ldg(rowbits + (size_t)(rb * 128 + rl) * 32 + cw + wq);
        else         mask = rowActive ? __ldg(dwords + cw + wq) : 0u;
        if (tid < 128) edst_s[tid] = g_edst[inst * NN + c * 128 + tid];
        __syncthreads();

        // scatter edges into own fragment slots (no cross-thread hazard)
        // byte(k): (kl>>4)*512 + ((kl>>1)&3)*16 + ((kl>>3)&1)*8 + (kl&1)*2
        while (mask) {
            const int kl = __ffs(mask) - 1; mask &= mask - 1;
            float l = es + edst_s[wq * 32 + kl];
            l = fmaxf(l, 0.01f * l);
            const float w = __expf(l) - 1.0f;
            wsum_local += w;
            unsigned short hv;
            asm("cvt.rn.bf16.f32 %0, %1;" : "=h"(hv) : "f"(w));
            const uint32_t off = byteBase + (uint32_t)(((kl & 16) << 5) + ((kl & 6) << 3)
                                                       + (kl & 8) + ((kl & 1) << 1));
            *(unsigned short*)(AwB + off) = hv;
        }
        __syncthreads();

        // MMAs: A from smem, B from gmem (L2-resident fragments)
        const uint32_t* Bg = Bg0 + (size_t)c * 8192;
        #pragma unroll
        for (int kt = 0; kt < 8; kt++) {
            uint4 a[2]; uint2 bb[4];
            #pragma unroll
            for (int i = 0; i < 2; i++)
                a[i] = *(const uint4*)(Aw + (((wm * 2 + i) * 8 + kt) * 32 + lane) * 4);
            #pragma unroll
            for (int j = 0; j < 4; j++)
                bb[j] = *(const uint2*)(Bg + (((wn * 4 + j) * 8 + kt) * 32 + lane) * 2);
            #pragma unroll
            for (int i = 0; i < 2; i++)
                #pragma unroll
                for (int j = 0; j < 4; j++)
                    mma_bf16(acc[i][j], a[i], bb[j]);
        }
    }

    atomicAdd(&wsum_s[rl], wsum_local);
    __syncthreads();

    // ---- epilogue: (Htot + U) * scale / (1024 + Wsum) ----
    const int g = lane >> 2, t4 = lane & 3;
    float* part = g_part[op] + ((size_t)b * NN) * FF;
    #pragma unroll
    for (int i = 0; i < 2; i++) {
        const int rloc = (wm * 2 + i) * 16 + g;
        const float inv0 = scale / (1024.0f + wsum_s[rloc]);
        const float inv1 = scale / (1024.0f + wsum_s[rloc + 8]);
        const int m0 = rb * 128 + rloc;
        #pragma unroll
        for (int j = 0; j < 4; j++) {
            const int f = (wn * 4 + j) * 8 + t4 * 2;
            const float2 ht = *(const float2*)(g_Htot + inst * FF + f);
            float2 lo = make_float2((ht.x + acc[i][j].x) * inv0,
                                    (ht.y + acc[i][j].y) * inv0);
            float2 hi = make_float2((ht.x + acc[i][j].z) * inv1,
                                    (ht.y + acc[i][j].w) * inv1);
            *(float2*)(part + (size_t)m0 * FF + f)       = lo;
            *(float2*)(part + (size_t)(m0 + 8) * FF + f) = hi;
        }
    }
}

// =========================== final reduce + ReLU ================================
__global__ __launch_bounds__(256) void reduce_kernel(float* __restrict__ out)
{
    const int i = blockIdx.x * blockDim.x + threadIdx.x;   // float4 index
    float4 v = ((const float4*)g_outacc)[i];
    #pragma unroll
    for (int op = 0; op < 12; op++) {
        float4 p = ((const float4*)(g_part[op]))[i];
        v.x += p.x; v.y += p.y; v.z += p.z; v.w += p.w;
    }
    v.x = fmaxf(v.x, 0.f); v.y = fmaxf(v.y, 0.f);
    v.z = fmaxf(v.z, 0.f); v.w = fmaxf(v.w, 0.f);
    ((float4*)out)[i] = v;
}

// ================================================================================
extern "C" void kernel_launch(void* const* d_in, const int* in_sizes, int n_in,
                              void* d_out, int out_size)
{
    const float* batch_x    = (const float*)d_in[0];
    const float* batch_adjs = (const float*)d_in[1];
    const float* fc_w       = (const float*)d_in[2];
    const float* fc_b       = (const float*)d_in[3];
    const float* att_w      = (const float*)d_in[4];
    const float* att_b      = (const float*)d_in[5];
    const float* fwd_fc_w   = (const float*)d_in[6];
    const float* fwd_fc_b   = (const float*)d_in[7];
    const float* fwd_att_w  = (const float*)d_in[8];
    const float* fwd_att_b  = (const float*)d_in[9];
    const float* bwd_fc_w   = (const float*)d_in[10];
    const float* bwd_fc_b   = (const float*)d_in[11];
    const float* bwd_att_w  = (const float*)d_in[12];
    const float* bwd_att_b  = (const float*)d_in[13];
    const float* self_w     = (const float*)d_in[14];
    const float* self_b     = (const float*)d_in[15];
    const float* bias       = (const float*)d_in[16];
    float* out = (float*)d_out;

    static bool attr_done = false;
    if (!attr_done) {
        cudaFuncSetAttribute(gemm_kernel, cudaFuncAttributeMaxDynamicSharedMemorySize, GEMM_SMEM);
        attr_done = true;
    }

    bitpack_kernel<<<dim3(32, 7, 8), 256>>>(batch_adjs);                  // launch 0
    gemm_kernel<<<dim3(8, 13, 8), 512, GEMM_SMEM>>>(batch_x, fc_w, fc_b, // launch 1
                                                    fwd_fc_w, fwd_fc_b,
                                                    bwd_fc_w, bwd_fc_b,
                                                    self_w, self_b, bias,
                                                    att_w, att_b, fwd_att_w,
                                                    fwd_att_b, bwd_att_w, bwd_att_b);
    hconv_kernel<<<dim3(8, 12, 8), 256>>>();                              // launch 2
    agg_kernel<<<dim3(8, 12, 8), 512>>>();                                // launch 3 (ncu target)
    reduce_kernel<<<1024, 256>>>(out);                                    // launch 4
}

// round 13
// speedup vs baseline: 1.8070x; 1.0357x over previous
#include <cuda_runtime.h>
#include <cuda_bf16.h>
#include <stdint.h>

#define BATCH 8
#define NN    1024
#define FF    128

// ---------------- scratch (no allocations allowed -> __device__ globals) --------
__device__ uint32_t g_Hbf[(size_t)BATCH * 12 * 8 * 8192];  // 25 MB bf16 B-fragments
__device__ float    g_outacc[(size_t)BATCH * NN * FF];     // 4 MB (self contribution)
__device__ float    g_part[12][(size_t)BATCH * NN * FF];   // 48 MB per-op partials
__device__ float    g_esrc[BATCH * 12 * NN];
__device__ float    g_edst[BATCH * 12 * NN];
__device__ float    g_Htot[BATCH * 12 * FF];
__device__ uint32_t g_rowbits[(size_t)BATCH * 6 * NN * 32];  // rel 0-2, 6-8 row masks
__device__ uint32_t g_bitsT[(size_t)BATCH * 3 * NN * 32];    // rel 6-8 transposed masks
__device__ uint32_t g_dbits[BATCH * 3 * 32];                 // diag masks (rel 3-5)

// pack two fp32 into bf16x2 word (lo -> low half, hi -> high half)
__device__ __forceinline__ uint32_t pack_bf16x2(float lo, float hi)
{
    uint32_t r;
    asm("cvt.rn.bf16x2.f32 %0, %1, %2;" : "=r"(r) : "f"(hi), "f"(lo));
    return r;
}

// =========== fused bitpack: row masks, transposed masks, diag, Htot zero ========
__global__ __launch_bounds__(256) void bitpack_kernel(const float* __restrict__ adjs)
{
    const int slab = blockIdx.x, y = blockIdx.y, b = blockIdx.z;
    const int warp = threadIdx.x >> 5, lane = threadIdx.x & 31;

    if (y == 6) {
        if (slab < 3) {                       // diag masks for rel 3..5
            #pragma unroll
            for (int rr = 0; rr < 4; rr++) {
                const int i = rr * 256 + threadIdx.x;
                float v = adjs[(((size_t)(b * 9 + 3 + slab)) * NN + i) * NN + i];
                unsigned m = __ballot_sync(0xffffffffu, v > 0.f);
                if (lane == 0) g_dbits[(b * 3 + slab) * 32 + (i >> 5)] = m;
            }
        } else if (slab == 3 && b == 0) {     // zero Htot (before gemm's atomics)
            for (int t = threadIdx.x; t < BATCH * 12 * FF; t += 256) g_Htot[t] = 0.f;
        }
        return;
    }

    const bool doT = (y >= 3);
    const int rel = doT ? (y + 3) : y;        // y 0-2 -> rel 0-2 ; y 3-5 -> rel 6-8
    __shared__ uint32_t sw[32 * 32];

    #pragma unroll
    for (int rr = 0; rr < 4; rr++) {
        const int row = slab * 32 + warp * 4 + rr;
        const float* rp = adjs + (((size_t)(b * 9 + rel)) * NN + row) * NN;
        uint32_t myw = 0;
        #pragma unroll 4
        for (int it = 0; it < 32; it++) {
            float v = rp[it * 32 + lane];
            unsigned mm = __ballot_sync(0xffffffffu, v > 0.f);
            if (lane == it) myw = mm;
        }
        g_rowbits[(((size_t)(b * 6 + y)) * NN + row) * 32 + lane] = myw;
        if (doT) sw[(warp * 4 + rr) * 32 + lane] = myw;
    }
    if (doT) {
        __syncthreads();
        for (int c = threadIdx.x; c < NN; c += 256) {
            const int word = c >> 5, bit = c & 31;
            uint32_t t = 0;
            #pragma unroll
            for (int r = 0; r < 32; r++)
                t |= ((sw[r * 32 + word] >> bit) & 1u) << r;
            g_bitsT[(((size_t)(b * 3 + (y - 3))) * NN + c) * 32 + slab] = t;
        }
    }
}

// =============================== tf32 GEMM ======================================
// Computes H, writes it DIRECTLY as bf16 MMA-B-fragments (hconv fused), plus
// Htot column sums and the esrc/edst attention vectors, all in one epilogue.
__device__ __forceinline__ uint32_t f2tf32(float f)
{
    uint32_t r;
    asm("cvt.rna.tf32.f32 %0, %1;" : "=r"(r) : "f"(f));
    return r;
}

__device__ __forceinline__ void mma_tf32(float4& d, const uint4 a, const uint2 b)
{
    asm volatile(
        "mma.sync.aligned.m16n8k8.row.col.f32.tf32.tf32.f32 "
        "{%0,%1,%2,%3}, {%4,%5,%6,%7}, {%8,%9}, {%0,%1,%2,%3};"
        : "+f"(d.x), "+f"(d.y), "+f"(d.z), "+f"(d.w)
        : "r"(a.x), "r"(a.y), "r"(a.z), "r"(a.w), "r"(b.x), "r"(b.y));
}

#define GEMM_SMEM (32768 * 4)

__global__ __launch_bounds__(512) void gemm_kernel(
    const float* __restrict__ x,
    const float* __restrict__ fc_w,  const float* __restrict__ fc_b,
    const float* __restrict__ fwd_w, const float* __restrict__ fwd_b,
    const float* __restrict__ bwd_w, const float* __restrict__ bwd_b,
    const float* __restrict__ self_w, const float* __restrict__ self_b,
    const float* __restrict__ bias,
    const float* __restrict__ att_w,  const float* __restrict__ att_b,
    const float* __restrict__ fwd_aw, const float* __restrict__ fwd_ab,
    const float* __restrict__ bwd_aw, const float* __restrict__ bwd_ab)
{
    extern __shared__ uint32_t sm[];
    uint32_t* As = sm;
    uint32_t* Ws = sm + 16384;

    const int rb = blockIdx.x, r = blockIdx.y, b = blockIdx.z;
    const int tid = threadIdx.x;

    const float* X = x + (size_t)b * NN * FF + (size_t)rb * 128 * FF;
    const float* Wp; const float* bv; const float* bv2 = nullptr;
    if (r < 6)       { Wp = fc_w  + r * FF * FF;       bv = fc_b  + r * FF; }
    else if (r < 9)  { Wp = fwd_w + (r - 6) * FF * FF; bv = fwd_b + (r - 6) * FF; }
    else if (r < 12) { Wp = bwd_w + (r - 9) * FF * FF; bv = bwd_b + (r - 9) * FF; }
    else             { Wp = self_w; bv = self_b; bv2 = bias; }

    for (int t = tid; t < 4096; t += 512) {
        const int row = t >> 5;
        const int c = (t & 31) << 2;
        float4 v = *(const float4*)(X + (size_t)row * FF + c);
        const int m = row >> 4, lr = row & 15;
        const int s = c >> 3;
        const int reg = (lr >> 3) + ((c & 4) ? 2 : 0);
        uint32_t* base = As + (((m << 4) + s) << 7) + (((lr & 7) << 2) << 2) + reg;
        base[0]  = f2tf32(v.x);
        base[4]  = f2tf32(v.y);
        base[8]  = f2tf32(v.z);
        base[12] = f2tf32(v.w);
    }
    for (int t = tid; t < 4096; t += 512) {
        const int n = t >> 5;
        const int k = (t & 31) << 2;
        float4 v = *(const float4*)(Wp + (size_t)n * FF + k);
        const int nt = n >> 3;
        const int s = k >> 3;
        const int reg = (k & 4) ? 1 : 0;
        uint32_t* base = Ws + (((nt << 4) + s) << 6) + (((n & 7) << 2) << 1) + reg;
        base[0] = f2tf32(v.x);
        base[2] = f2tf32(v.y);
        base[4] = f2tf32(v.z);
        base[6] = f2tf32(v.w);
    }
    __syncthreads();

    const int warp = tid >> 5, lane = tid & 31;
    const int wm = warp >> 2, wn = warp & 3;

    float4 acc[2][4];
    #pragma unroll
    for (int i = 0; i < 2; i++)
        #pragma unroll
        for (int j = 0; j < 4; j++) acc[i][j] = make_float4(0.f, 0.f, 0.f, 0.f);

    #pragma unroll
    for (int s = 0; s < 16; s++) {
        uint4 a[2]; uint2 bb[4];
        #pragma unroll
        for (int i = 0; i < 2; i++)
            a[i] = *(const uint4*)(As + ((((wm * 2 + i) << 4) + s) << 7) + (lane << 2));
        #pragma unroll
        for (int j = 0; j < 4; j++)
            bb[j] = *(const uint2*)(Ws + ((((wn * 4 + j) << 4) + s) << 6) + (lane << 1));
        #pragma unroll
        for (int i = 0; i < 2; i++)
            #pragma unroll
            for (int j = 0; j < 4; j++)
                mma_tf32(acc[i][j], a[i], bb[j]);
    }

    const int g = lane >> 2, t4 = lane & 3;
    float b0[4], b1[4];
    #pragma unroll
    for (int j = 0; j < 4; j++) {
        const int col = (wn * 4 + j) * 8 + 2 * t4;
        b0[j] = bv[col];     b1[j] = bv[col + 1];
        if (bv2) { b0[j] += bv2[col]; b1[j] += bv2[col + 1]; }
    }

    if (r == 12) {
        float* dst = g_outacc + (size_t)b * NN * FF;
        #pragma unroll
        for (int i = 0; i < 2; i++) {
            const int row0 = rb * 128 + (wm * 2 + i) * 16 + g;
            #pragma unroll
            for (int j = 0; j < 4; j++) {
                const int col = (wn * 4 + j) * 8 + 2 * t4;
                float2 lo = make_float2(acc[i][j].x + b0[j], acc[i][j].y + b1[j]);
                float2 hi = make_float2(acc[i][j].z + b0[j], acc[i][j].w + b1[j]);
                *(float2*)(dst + (size_t)row0 * FF + col)       = lo;
                *(float2*)(dst + (size_t)(row0 + 8) * FF + col) = hi;
            }
        }
        return;
    }

    // ---- fused hconv: stage fp32 H tile in smem, emit bf16 B-fragments --------
    {
        __syncthreads();                       // all warps done reading As/Ws
        float* smf = (float*)sm;               // 128 rows x pitch 132 = 16896 floats
        #pragma unroll
        for (int i = 0; i < 2; i++) {
            const int rl_ = (wm * 2 + i) * 16 + g;
            #pragma unroll
            for (int j = 0; j < 4; j++) {
                const int col = (wn * 4 + j) * 8 + 2 * t4;
                *(float2*)(smf + rl_ * 132 + col) =
                    make_float2(acc[i][j].x + b0[j], acc[i][j].y + b1[j]);
                *(float2*)(smf + (rl_ + 8) * 132 + col) =
                    make_float2(acc[i][j].z + b0[j], acc[i][j].w + b1[j]);
            }
        }
        __syncthreads();
        uint32_t* dstf = g_Hbf + ((size_t)(b * 12 + r) * 8 + rb) * 8192;
        #pragma unroll
        for (int it = 0; it < 16; it++) {
            const int o = it * 512 + tid;
            const int rg = o & 1, l2 = (o >> 1) & 31, kt = (o >> 6) & 7, nt = o >> 9;
            const int tt = l2 & 3, g2 = l2 >> 2;
            const int rp = kt * 8 + rg * 4 + tt;    // row pair (2rp, 2rp+1)
            const int f = nt * 8 + g2;
            dstf[o] = pack_bf16x2(smf[2 * rp * 132 + f], smf[(2 * rp + 1) * 132 + f]);
        }
    }

    // ---- Htot column sums (register reduction + atomics) -----------------------
    {
        const int inst = b * 12 + r;
        #pragma unroll
        for (int j = 0; j < 4; j++) {
            float s0 = 0.f, s1 = 0.f;
            #pragma unroll
            for (int i = 0; i < 2; i++) {
                s0 += acc[i][j].x + acc[i][j].z;
                s1 += acc[i][j].y + acc[i][j].w;
            }
            #pragma unroll
            for (int off = 16; off >= 4; off >>= 1) {
                s0 += __shfl_down_sync(0xffffffffu, s0, off);
                s1 += __shfl_down_sync(0xffffffffu, s1, off);
            }
            if (lane < 4) {
                const int col = (wn * 4 + j) * 8 + 2 * lane;
                atomicAdd(&g_Htot[inst * FF + col],     s0 + 32.f * bv[col]);
                atomicAdd(&g_Htot[inst * FF + col + 1], s1 + 32.f * bv[col + 1]);
            }
        }
    }

    // ---- fused attention e-vectors (esrc/edst) for r<6; r==5 also serves ops 6-11
    if (r < 6) {
        float* es_s = (float*)sm;         // reuse smem (synced inside loop)
        float* ed_s = ((float*)sm) + 128;
        const int nsets = (r == 5) ? 7 : 1;
        for (int set = 0; set < nsets; set++) {
            const int opx = (set == 0) ? r : 5 + set;
            const float* w; float ab;
            if (opx < 6)      { w = att_w  + opx * 2 * FF;       ab = att_b[opx]; }
            else if (opx < 9) { w = fwd_aw + (opx - 6) * 2 * FF; ab = fwd_ab[opx - 6]; }
            else              { w = bwd_aw + (opx - 9) * 2 * FF; ab = bwd_ab[opx - 9]; }
            float c1 = 0.f, c2 = 0.f;
            #pragma unroll
            for (int q = 0; q < 4; q++) {
                float bvv = bv[lane + 32 * q];
                c1 += bvv * w[lane + 32 * q];
                c2 += bvv * w[FF + lane + 32 * q];
            }
            #pragma unroll
            for (int off = 16; off > 0; off >>= 1) {
                c1 += __shfl_xor_sync(0xffffffffu, c1, off);
                c2 += __shfl_xor_sync(0xffffffffu, c2, off);
            }
            c1 += ab;
            __syncthreads();
            if (tid < 128) { es_s[tid] = 0.f; ed_s[tid] = 0.f; }
            __syncthreads();
            #pragma unroll
            for (int i = 0; i < 2; i++) {
                const int rl = (wm * 2 + i) * 16 + g;
                float p1a = 0.f, p2a = 0.f, p1b = 0.f, p2b = 0.f;
                #pragma unroll
                for (int j = 0; j < 4; j++) {
                    const int col = (wn * 4 + j) * 8 + 2 * t4;
                    const float w1a = w[col],      w1b = w[col + 1];
                    const float w2a = w[FF + col], w2b = w[FF + col + 1];
                    p1a += acc[i][j].x * w1a + acc[i][j].y * w1b;
                    p2a += acc[i][j].x * w2a + acc[i][j].y * w2b;
                    p1b += acc[i][j].z * w1a + acc[i][j].w * w1b;
                    p2b += acc[i][j].z * w2a + acc[i][j].w * w2b;
                }
                atomicAdd(&es_s[rl], p1a);     atomicAdd(&ed_s[rl], p2a);
                atomicAdd(&es_s[rl + 8], p1b); atomicAdd(&ed_s[rl + 8], p2b);
            }
            __syncthreads();
            if (tid < 128) {
                g_esrc[(b * 12 + opx) * NN + rb * 128 + tid] = es_s[tid] + c1;
                g_edst[(b * 12 + opx) * NN + rb * 128 + tid] = ed_s[tid] + c2;
            }
        }
    }
}

// ============== sparse-scatter MMA aggregation (double-buffered) ================
// Scatter of chunk c+1 overlaps MMAs of chunk c; edst via __ldg (L1-resident).
__device__ __forceinline__ void mma_bf16(float4& d, const uint4 a, const uint2 b)
{
    asm volatile(
        "mma.sync.aligned.m16n8k16.row.col.f32.bf16.bf16.f32 "
        "{%0,%1,%2,%3}, {%4,%5,%6,%7}, {%8,%9}, {%0,%1,%2,%3};"
        : "+f"(d.x), "+f"(d.y), "+f"(d.z), "+f"(d.w)
        : "r"(a.x), "r"(a.y), "r"(a.z), "r"(a.w), "r"(b.x), "r"(b.y));
}

#define AGG_SMEM (65536)

__global__ __launch_bounds__(512, 2) void agg_kernel()
{
    extern __shared__ uint32_t smd[];       // Aw double buffer: 2 x 8192 words
    __shared__ float wsum_s[128];

    const int rb = blockIdx.x, op = blockIdx.y, b = blockIdx.z;
    const int inst = b * 12 + op;
    const int tid = threadIdx.x;
    const int rl = tid >> 2, wq = tid & 3;     // row-local 0..127, k-word 0..3

    const uint32_t* rowbits = nullptr;
    const uint32_t* dwords = nullptr;
    float scale = 1.0f;
    if (op < 3)      rowbits = g_rowbits + (((size_t)(b * 6 + op)) * NN) * 32;
    else if (op < 6) dwords = g_dbits + (b * 3 + (op - 3)) * 32;
    else if (op < 9) { rowbits = g_rowbits + (((size_t)(b * 6 + op - 3)) * NN) * 32; scale = 0.5f; }
    else             { rowbits = g_bitsT + (((size_t)(b * 3 + op - 9)) * NN) * 32;   scale = 0.5f; }

    const int warp = tid >> 5, lane = tid & 31;
    const int wm = warp >> 2, wn = warp & 3;          // warp tile 32 rows x 32 feats
    const uint32_t* Bg0 = g_Hbf + (size_t)inst * 8 * 8192;

    // per-thread scatter addressing constants (owned 16 Aw words, disjoint)
    const int mt = rl >> 4, gg = rl & 7, rb0 = (rl >> 3) & 1;
    const uint32_t byteBase = 4u * (uint32_t)(mt * 1024 + gg * 16 + rb0) + wq * 1024u;

    const float es = g_esrc[inst * NN + rb * 128 + rl];
    bool rowActive = true;
    if (dwords) {
        const int row = rb * 128 + rl;
        rowActive = ((__ldg(dwords + (row >> 5)) >> (row & 31)) & 1u) != 0;
    }
    const uint32_t* mask_base = rowbits ? (rowbits + (size_t)(rb * 128 + rl) * 32 + wq)
                                        : nullptr;
    const float* edst_base = g_edst + inst * NN + wq * 32;

    if (tid < 128) wsum_s[tid] = 0.f;
    float wsum_local = 0.f;

    // scatter chunk cc into buffer buf (writes only this thread's owned slots)
    auto scatter = [&](int cc, uint32_t* buf) {
        uint32_t mask;
        if (rowbits) mask = __ldg(mask_base + cc * 4);
        else         mask = rowActive ? __ldg(dwords + cc * 4 + wq) : 0u;
        const float* ep = edst_base + cc * 128;
        char* baseB = (char*)buf;
        while (mask) {
            const int kl = __ffs(mask) - 1; mask &= mask - 1;
            float l = es + __ldg(ep + kl);
            l = fmaxf(l, 0.01f * l);
            const float w = __expf(l) - 1.0f;
            wsum_local += w;
            unsigned short hv;
            asm("cvt.rn.bf16.f32 %0, %1;" : "=h"(hv) : "f"(w));
            const uint32_t off = byteBase + (uint32_t)(((kl & 16) << 5) + ((kl & 6) << 3)
                                                       + (kl & 8) + ((kl & 1) << 1));
            *(unsigned short*)(baseB + off) = hv;
        }
    };

    float4 acc[2][4];
    #pragma unroll
    for (int i = 0; i < 2; i++)
        #pragma unroll
        for (int j = 0; j < 4; j++) acc[i][j] = make_float4(0.f, 0.f, 0.f, 0.f);

    // prologue: zero both buffers, scatter chunk 0
    {
        const uint4 z = make_uint4(0u, 0u, 0u, 0u);
        #pragma unroll
        for (int t = 0; t < 4; t++) {
            *(uint4*)(smd + (tid + t * 512) * 4) = z;
            *(uint4*)(smd + 8192 + (tid + t * 512) * 4) = z;
        }
    }
    __syncthreads();
    scatter(0, smd);
    __syncthreads();

    for (int c = 0; c < 8; c++) {
        uint32_t* cur = (c & 1) ? (smd + 8192) : smd;
        uint32_t* nxt = (c & 1) ? smd : (smd + 8192);

        if (c < 7) scatter(c + 1, nxt);    // overlaps with MMAs below

        const uint32_t* Bg = Bg0 + (size_t)c * 8192;
        #pragma unroll
        for (int kt = 0; kt < 8; kt++) {
            uint4 a[2]; uint2 bb[4];
            #pragma unroll
            for (int i = 0; i < 2; i++)
                a[i] = *(const uint4*)(cur + (((wm * 2 + i) * 8 + kt) * 32 + lane) * 4);
            #pragma unroll
            for (int j = 0; j < 4; j++)
                bb[j] = *(const uint2*)(Bg + (((wn * 4 + j) * 8 + kt) * 32 + lane) * 2);
            #pragma unroll
            for (int i = 0; i < 2; i++)
                #pragma unroll
                for (int j = 0; j < 4; j++)
                    mma_bf16(acc[i][j], a[i], bb[j]);
        }
        __syncthreads();                   // scatter(c+1) + MMA(c) complete

        if (c < 6) {                       // re-zero dead buffer for chunk c+2
            const uint4 z = make_uint4(0u, 0u, 0u, 0u);
            #pragma unroll
            for (int t = 0; t < 4; t++)
                *(uint4*)(cur + (tid + t * 512) * 4) = z;
            __syncthreads();
        }
    }

    atomicAdd(&wsum_s[rl], wsum_local);
    __syncthreads();

    // ---- epilogue: (Htot + U) * scale / (1024 + Wsum) ----
    const int g = lane >> 2, t4 = lane & 3;
    float* part = g_part[op] + ((size_t)b * NN) * FF;
    #pragma unroll
    for (int i = 0; i < 2; i++) {
        const int rloc = (wm * 2 + i) * 16 + g;
        const float inv0 = scale / (1024.0f + wsum_s[rloc]);
        const float inv1 = scale / (1024.0f + wsum_s[rloc + 8]);
        const int m0 = rb * 128 + rloc;
        #pragma unroll
        for (int j = 0; j < 4; j++) {
            const int f = (wn * 4 + j) * 8 + t4 * 2;
            const float2 ht = *(const float2*)(g_Htot + inst * FF + f);
            float2 lo = make_float2((ht.x + acc[i][j].x) * inv0,
                                    (ht.y + acc[i][j].y) * inv0);
            float2 hi = make_float2((ht.x + acc[i][j].z) * inv1,
                                    (ht.y + acc[i][j].w) * inv1);
            *(float2*)(part + (size_t)m0 * FF + f)       = lo;
            *(float2*)(part + (size_t)(m0 + 8) * FF + f) = hi;
        }
    }
}

// =========================== final reduce + ReLU ================================
__global__ __launch_bounds__(256) void reduce_kernel(float* __restrict__ out)
{
    const int i = blockIdx.x * blockDim.x + threadIdx.x;   // float4 index
    float4 v = ((const float4*)g_outacc)[i];
    #pragma unroll
    for (int op = 0; op < 12; op++) {
        float4 p = ((const float4*)(g_part[op]))[i];
        v.x += p.x; v.y += p.y; v.z += p.z; v.w += p.w;
    }
    v.x = fmaxf(v.x, 0.f); v.y = fmaxf(v.y, 0.f);
    v.z = fmaxf(v.z, 0.f); v.w = fmaxf(v.w, 0.f);
    ((float4*)out)[i] = v;
}

// ================================================================================
extern "C" void kernel_launch(void* const* d_in, const int* in_sizes, int n_in,
                              void* d_out, int out_size)
{
    const float* batch_x    = (const float*)d_in[0];
    const float* batch_adjs = (const float*)d_in[1];
    const float* fc_w       = (const float*)d_in[2];
    const float* fc_b       = (const float*)d_in[3];
    const float* att_w      = (const float*)d_in[4];
    const float* att_b      = (const float*)d_in[5];
    const float* fwd_fc_w   = (const float*)d_in[6];
    const float* fwd_fc_b   = (const float*)d_in[7];
    const float* fwd_att_w  = (const float*)d_in[8];
    const float* fwd_att_b  = (const float*)d_in[9];
    const float* bwd_fc_w   = (const float*)d_in[10];
    const float* bwd_fc_b   = (const float*)d_in[11];
    const float* bwd_att_w  = (const float*)d_in[12];
    const float* bwd_att_b  = (const float*)d_in[13];
    const float* self_w     = (const float*)d_in[14];
    const float* self_b     = (const float*)d_in[15];
    const float* bias       = (const float*)d_in[16];
    float* out = (float*)d_out;

    static bool attr_done = false;
    if (!attr_done) {
        cudaFuncSetAttribute(gemm_kernel, cudaFuncAttributeMaxDynamicSharedMemorySize, GEMM_SMEM);
        cudaFuncSetAttribute(agg_kernel, cudaFuncAttributeMaxDynamicSharedMemorySize, AGG_SMEM);
        attr_done = true;
    }

    bitpack_kernel<<<dim3(32, 7, 8), 256>>>(batch_adjs);                  // launch 0
    gemm_kernel<<<dim3(8, 13, 8), 512, GEMM_SMEM>>>(batch_x, fc_w, fc_b, // launch 1
                                                    fwd_fc_w, fwd_fc_b,
                                                    bwd_fc_w, bwd_fc_b,
                                                    self_w, self_b, bias,
                                                    att_w, att_b, fwd_att_w,
                                                    fwd_att_b, bwd_att_w, bwd_att_b);
    agg_kernel<<<dim3(8, 12, 8), 512, AGG_SMEM>>>();                      // launch 2
    reduce_kernel<<<1024, 256>>>(out);                                    // launch 3
}